// round 9
// baseline (speedup 1.0000x reference)
#include <cuda_runtime.h>
#include <cstdint>

#define BB   64
#define TT   512
#define HH   128
#define EMBD 128

// ---------------- scratch (device globals: allocation-free) ----------------
__device__ float g_xe[BB * TT * EMBD];          // embed output
__device__ float g_y0[BB * TT * 2 * HH];        // layer0 output
__device__ float g_y1[BB * TT * 2 * HH];        // layer1 output
__device__ float g_y2[BB * TT * 2 * HH];        // layer2 output
__device__ float g_xg[2ull * BB * TT * 4 * HH]; // input-GEMM gates

typedef unsigned long long u64;

__device__ __forceinline__ u64 fma2(u64 a, u64 b, u64 c) {
    u64 d;
    asm("fma.rn.f32x2 %0, %1, %2, %3;" : "=l"(d) : "l"(a), "l"(b), "l"(c));
    return d;
}
__device__ __forceinline__ u64 pack2(float lo, float hi) {
    u64 r;
    asm("mov.b64 %0, {%1, %2};" : "=l"(r) : "f"(lo), "f"(hi));
    return r;
}
__device__ __forceinline__ void unpack2(u64 v, float& lo, float& hi) {
    asm("mov.b64 {%0, %1}, %2;" : "=f"(lo), "=f"(hi) : "l"(v));
}
__device__ __forceinline__ float sigf(float x) {
    return __fdividef(1.f, 1.f + __expf(-x));
}
__device__ __forceinline__ float tanh_f(float x) {
    float cl = fminf(fmaxf(x, -15.f), 15.f);
    float e  = __expf(2.f * cl);
    return __fdividef(e - 1.f, e + 1.f);
}

// ---------------- embedding lookup ----------------
__global__ void embed_kernel(const int* __restrict__ X, const float* __restrict__ emb,
                             float* __restrict__ out) {
    int row  = blockIdx.x * 4 + (threadIdx.x >> 5);
    int lane = threadIdx.x & 31;
    int tok  = X[row];
    float4 v = reinterpret_cast<const float4*>(emb + (size_t)tok * EMBD)[lane];
    reinterpret_cast<float4*>(out + (size_t)row * EMBD)[lane] = v;
}

// dummy launch: shifts ncu's (-s 5 -c 1) capture window onto the layer-1 scan kernel
__global__ void dummy_kernel() {}

// ---------------- input GEMM:  C[m][n] = A[m][:] . W[n][:] + (bih[n]+bhh[n]) ------------
// A: [32768 x K] row-major, W(per dir): [512 x K] row-major, C: [32768 x 512] row-major.
// blockIdx.z = direction. 128x128 tile, 256 threads, 8x8 microtile.
// DOUBLE-BUFFERED smem (dynamic, ~101KB): LDG prefetch of tile kt+1 issued before
// computing tile kt; regs->smem store into alternate buffer; ONE sync per tile.
// As2 holds A pre-duplicated as (a,a) u64 pairs (one LDS.128 = 2 ready f32x2
// multiplicands, zero pack MOVs in the hot loop). Bs [k][n] transposed.
template <int K>
__global__ void __launch_bounds__(256) gemm_kernel(
    const float* __restrict__ Amat, const float* __restrict__ Wbase,
    const float* __restrict__ bih_base, const float* __restrict__ bhh_base,
    float* __restrict__ Cbase) {
    extern __shared__ __align__(16) char smem_raw[];
    u64*   As2 = reinterpret_cast<u64*>(smem_raw);                        // [2][128][34]
    float* Bs  = reinterpret_cast<float*>(smem_raw + 2 * 128 * 34 * 8);   // [2][32][132]

    constexpr int NT = K / 32;

    int z = blockIdx.z;
    const float* Wmat = Wbase + (size_t)z * 512 * K;
    const float* bih  = bih_base + (size_t)z * 512;
    const float* bhh  = bhh_base + (size_t)z * 512;
    float*       Cmat = Cbase + (size_t)z * BB * TT * 512;

    int tid = threadIdx.x;
    int m0  = blockIdx.x * 128;
    int n0  = blockIdx.y * 128;
    int tx  = tid & 15;             // n micro
    int ty  = tid >> 4;             // m micro
    int r8  = tid >> 3;             // 0..31  (load row)
    int c8  = tid & 7;              // 0..7   (load k-float4)

    const float* aptr = Amat + (size_t)(m0 + r8) * K + c8 * 4;
    const float* wptr = Wmat + (size_t)(n0 + r8) * K + c8 * 4;

    float bias[8];
#pragma unroll
    for (int j = 0; j < 4; j++) {
        bias[j]     = bih[n0 + tx * 4 + j]      + bhh[n0 + tx * 4 + j];
        bias[j + 4] = bih[n0 + 64 + tx * 4 + j] + bhh[n0 + 64 + tx * 4 + j];
    }

    u64 acc[8][4];
#pragma unroll
    for (int i = 0; i < 8; i++)
#pragma unroll
        for (int j = 0; j < 4; j++) acc[i][j] = 0ull;

    float4 a_pre[4], b_pre[4];

#define LOADTILE(kt)                                                                   \
    do {                                                                               \
        _Pragma("unroll")                                                              \
        for (int ii = 0; ii < 4; ii++) {                                               \
            a_pre[ii] = *reinterpret_cast<const float4*>(aptr + (size_t)ii * 32 * K + (kt) * 32); \
            b_pre[ii] = *reinterpret_cast<const float4*>(wptr + (size_t)ii * 32 * K + (kt) * 32); \
        }                                                                              \
    } while (0)

#define STORETILE(bufi)                                                                \
    do {                                                                               \
        _Pragma("unroll")                                                              \
        for (int ii = 0; ii < 4; ii++) {                                               \
            u64* arow = As2 + ((size_t)((bufi) * 128 + r8 + ii * 32)) * 34 + c8 * 4;   \
            arow[0] = pack2(a_pre[ii].x, a_pre[ii].x);                                 \
            arow[1] = pack2(a_pre[ii].y, a_pre[ii].y);                                 \
            arow[2] = pack2(a_pre[ii].z, a_pre[ii].z);                                 \
            arow[3] = pack2(a_pre[ii].w, a_pre[ii].w);                                 \
            float* bcol = Bs + ((size_t)((bufi) * 32 + c8 * 4)) * 132 + r8 + ii * 32;  \
            bcol[0 * 132] = b_pre[ii].x;                                               \
            bcol[1 * 132] = b_pre[ii].y;                                               \
            bcol[2 * 132] = b_pre[ii].z;                                               \
            bcol[3 * 132] = b_pre[ii].w;                                               \
        }                                                                              \
    } while (0)

    LOADTILE(0);
    STORETILE(0);
    __syncthreads();

    int buf = 0;
#pragma unroll
    for (int kt = 0; kt < NT; kt++) {
        if (kt + 1 < NT) LOADTILE(kt + 1);   // prefetch next tile (latency hidden by compute)

#pragma unroll
        for (int kp = 0; kp < 16; kp++) {   // k-pair: kk = 2*kp, 2*kp+1
            const float* brow0 = Bs + ((size_t)(buf * 32 + 2 * kp)) * 132;
            const float* brow1 = brow0 + 132;
            ulonglong2 b0A = *reinterpret_cast<const ulonglong2*>(brow0 + tx * 4);
            ulonglong2 b0B = *reinterpret_cast<const ulonglong2*>(brow0 + 64 + tx * 4);
            ulonglong2 b1A = *reinterpret_cast<const ulonglong2*>(brow1 + tx * 4);
            ulonglong2 b1B = *reinterpret_cast<const ulonglong2*>(brow1 + 64 + tx * 4);
#pragma unroll
            for (int i = 0; i < 8; i++) {
                ulonglong2 ad = *reinterpret_cast<const ulonglong2*>(
                    As2 + ((size_t)(buf * 128 + ty * 8 + i)) * 34 + kp * 2);
                acc[i][0] = fma2(ad.x, b0A.x, acc[i][0]);
                acc[i][1] = fma2(ad.x, b0A.y, acc[i][1]);
                acc[i][2] = fma2(ad.x, b0B.x, acc[i][2]);
                acc[i][3] = fma2(ad.x, b0B.y, acc[i][3]);
                acc[i][0] = fma2(ad.y, b1A.x, acc[i][0]);
                acc[i][1] = fma2(ad.y, b1A.y, acc[i][1]);
                acc[i][2] = fma2(ad.y, b1B.x, acc[i][2]);
                acc[i][3] = fma2(ad.y, b1B.y, acc[i][3]);
            }
        }

        if (kt + 1 < NT) {
            STORETILE(buf ^ 1);   // safe: prev-iteration sync separated readers of buf^1
            __syncthreads();
        }
        buf ^= 1;
    }
#undef LOADTILE
#undef STORETILE

#pragma unroll
    for (int i = 0; i < 8; i++) {
        float o[8];
#pragma unroll
        for (int j = 0; j < 4; j++) unpack2(acc[i][j], o[2 * j], o[2 * j + 1]);
#pragma unroll
        for (int j = 0; j < 8; j++) o[j] += bias[j];
        float* base = Cmat + (size_t)(m0 + ty * 8 + i) * 512 + n0;
        *reinterpret_cast<float4*>(base + tx * 4)      = make_float4(o[0], o[1], o[2], o[3]);
        *reinterpret_cast<float4*>(base + 64 + tx * 4) = make_float4(o[4], o[5], o[6], o[7]);
    }
}

// ---------------- recurrent scan: 2-CTA cluster per (dir, batch-pair) ----------------
// Weights REGISTER-RESIDENT (64 u64 k-pairs per thread). mbarrier handshake replaces
// barrier.cluster: each CTA owns one mbarrier (count=128); the peer's 128 epilogue
// threads remote release-arrive after their DSMEM h stores (per-thread release orders
// each store). Wait = try_wait.parity.acquire.cluster fast-path (~90 cyc vs
// UCGABAR_WAIT ~490), issued MID-dot so even that hides under FMA.
// Step 0 needs no wait (prologue loads full h locally): wait iff s>0, parity (s-1)&1;
// arrive iff s<TT-1. Counts balance: TT-1 phases x 128 arrives.
__global__ void __launch_bounds__(256) lstm_scan_kernel(
    const float* __restrict__ xg,   // [2][B][T][512]
    const float* __restrict__ whh,  // [2][512][128]
    const float* __restrict__ hx,   // [2][B][128]  (this layer)
    const float* __restrict__ cx,   // [2][B][128]
    float* __restrict__ y) {        // [B][T][256]
    __shared__ __align__(16) float hbuf[2][2][128]; // double-buffered h, [buf][b][k]
    __shared__ __align__(8)  float gbuf[256 * 2];   // gate exchange [gl][b]
    __shared__ float cbuf[2 * 64];                  // own-half cell state
    __shared__ __align__(8) u64 mbar;               // peer-arrival barrier (count=128)

    int tid = threadIdx.x;
    uint32_t r;
    asm("mov.u32 %0, %%cluster_ctarank;" : "=r"(r));
    int cid = blockIdx.x >> 1;
    int dir = cid >> 5;
    int b0  = (cid & 31) * 2;

    // ---- load this thread's weight row into registers (64 u64 k-pairs) ----
    int gl  = tid;
    int row = ((gl >> 6) << 7) + (int)r * 64 + (gl & 63);  // gate_q*128 + r*64 + u
    u64 w[64];
    {
        const ulonglong2* wq =
            reinterpret_cast<const ulonglong2*>(whh + ((size_t)dir * 512 + row) * 128);
#pragma unroll
        for (int i = 0; i < 32; i++) {
            ulonglong2 v = wq[i];
            w[2 * i]     = v.x;
            w[2 * i + 1] = v.y;
        }
    }

    uint32_t mbar_local = (uint32_t)__cvta_generic_to_shared(&mbar);
    uint32_t mbar_peer;
    asm("mapa.shared::cluster.u32 %0, %1, %2;"
        : "=r"(mbar_peer) : "r"(mbar_local), "r"(r ^ 1u));

    // ---- init mbarrier, h (full, both batches), c (own half) ----
    if (tid == 0) {
        asm volatile("mbarrier.init.shared.b64 [%0], %1;"
                     :: "r"(mbar_local), "r"(128u) : "memory");
    }
    {
        int bb = tid >> 7, k = tid & 127;
        hbuf[0][bb][k] = hx[((size_t)dir * BB + b0 + bb) * HH + k];
        if (tid < 128) {
            int b = tid >> 6, u = tid & 63;
            cbuf[b * 64 + u] = cx[((size_t)dir * BB + b0 + b) * HH + (int)r * 64 + u];
        }
    }
    __syncthreads();
    // one-time full cluster sync: peer's mbarrier.init visible before any remote arrive
    asm volatile("barrier.cluster.arrive.aligned;" ::: "memory");
    asm volatile("barrier.cluster.wait.aligned;"   ::: "memory");

    int eb = tid >> 6;          // epilogue batch (tid<128)
    int eu = tid & 63;          // epilogue unit

    // hoisted xg walking pointer: advances by +512 (fwd) or -512 (bwd) per step
    const float* xp = xg + (((size_t)dir * BB + b0 + eb) * TT + (dir ? TT - 1 : 0)) * 512
                    + (int)r * 64 + eu;
    const intptr_t xstep = dir ? -512 : 512;
    // hoisted y walking pointer (same t ordering)
    float* yp = y + ((size_t)(b0 + eb) * TT + (dir ? TT - 1 : 0)) * 256
              + dir * 128 + (int)r * 64 + eu;
    const intptr_t ystep = dir ? -256 : 256;

    // spin-wait (acquire, cluster scope) on own mbarrier phase parity
#define MBAR_WAIT(par)                                                                \
    do {                                                                              \
        uint32_t _done;                                                               \
        asm volatile(                                                                 \
            "{\n\t.reg .pred p;\n\t"                                                  \
            "mbarrier.try_wait.parity.acquire.cluster.shared::cta.b64 p, [%1], %2;\n\t" \
            "selp.b32 %0, 1, 0, p;\n\t}"                                              \
            : "=r"(_done) : "r"(mbar_local), "r"((uint32_t)(par)) : "memory");        \
        while (!_done) {                                                              \
            asm volatile(                                                             \
                "{\n\t.reg .pred p;\n\t"                                              \
                "mbarrier.try_wait.parity.acquire.cluster.shared::cta.b64 p, [%1], %2, 0x989680;\n\t" \
                "selp.b32 %0, 1, 0, p;\n\t}"                                          \
                : "=r"(_done) : "r"(mbar_local), "r"((uint32_t)(par)) : "memory");    \
        }                                                                             \
    } while (0)

    // DOT over k-pairs [P0, P0+32): 2 LDS.128 + 4 FFMA2 per 2 pairs, w from regs.
#define DOT_HALF(P0)                                                                  \
    do {                                                                              \
        _Pragma("unroll")                                                             \
        for (int j = 0; j < 16; j++) {                                                \
            ulonglong2 hv0 =                                                          \
                *reinterpret_cast<const ulonglong2*>(&hbuf[cur][0][2 * ((P0) + 2 * j)]); \
            ulonglong2 hv1 =                                                          \
                *reinterpret_cast<const ulonglong2*>(&hbuf[cur][1][2 * ((P0) + 2 * j)]); \
            a0a = fma2(w[(P0) + 2 * j],     hv0.x, a0a);                              \
            a0b = fma2(w[(P0) + 2 * j + 1], hv0.y, a0b);                              \
            a1a = fma2(w[(P0) + 2 * j],     hv1.x, a1a);                              \
            a1b = fma2(w[(P0) + 2 * j + 1], hv1.y, a1b);                              \
        }                                                                             \
    } while (0)

    for (int s = 0; s < TT; s++) {
        int cur = s & 1;
        int nxt = cur ^ 1;

        // prefetch xg for this step's epilogue (hidden under the dot)
        float xv0 = 0.f, xv1 = 0.f, xv2 = 0.f, xv3 = 0.f;
        if (tid < 128) {
            xv0 = xp[0];
            xv1 = xp[128];
            xv2 = xp[256];
            xv3 = xp[384];
            xp += xstep;
        }

        u64 a0a = 0ull, a0b = 0ull, a1a = 0ull, a1b = 0ull;
        // own-written k-half first (no cluster dependency), wait hides mid-dot.
        // wait parity: phase s-1 completes via peer's end-of-step-(s-1) arrives
        if (r == 0) {
            DOT_HALF(0);                    // k [0,64) written locally by rank 0
            if (s > 0) MBAR_WAIT(nxt);      // (s-1)&1 == nxt
            DOT_HALF(32);                   // k [64,128) written remotely by rank 1
        } else {
            DOT_HALF(32);
            if (s > 0) MBAR_WAIT(nxt);
            DOT_HALF(0);
        }

        // complete gate values (lo=even-k partial, hi=odd-k partial)
        float e0, o0, e1, o1, e2, o2, e3, o3;
        unpack2(a0a, e0, o0);
        unpack2(a0b, e1, o1);
        unpack2(a1a, e2, o2);
        unpack2(a1b, e3, o3);
        float g0 = (e0 + o0) + (e1 + o1);   // batch 0
        float g1 = (e2 + o2) + (e3 + o3);   // batch 1
        *reinterpret_cast<float2*>(&gbuf[gl * 2]) = make_float2(g0, g1);
        __syncthreads();

        if (tid < 128) {
            int b = eb, u = eu;
            float gi = gbuf[(u)       * 2 + b] + xv0;
            float gf = gbuf[(64 + u)  * 2 + b] + xv1;
            float gg = gbuf[(128 + u) * 2 + b] + xv2;
            float go = gbuf[(192 + u) * 2 + b] + xv3;
            float i_ = sigf(gi), f_ = sigf(gf), o_ = sigf(go), gz = tanh_f(gg);
            float c = f_ * cbuf[b * 64 + u] + i_ * gz;
            cbuf[b * 64 + u] = c;
            float h = o_ * tanh_f(c);

            // layer output
            *yp = h;
            yp += ystep;

            if (s < TT - 1) {
                float* hl = &hbuf[nxt][b][(int)r * 64 + u];
                *hl = h;    // own half, local buffer
                // own half -> peer's buffer (DSMEM)
                uint32_t la = (uint32_t)__cvta_generic_to_shared(hl);
                uint32_t ra;
                asm("mapa.shared::cluster.u32 %0, %1, %2;" : "=r"(ra) : "r"(la), "r"(r ^ 1u));
                asm volatile("st.shared::cluster.f32 [%0], %1;" :: "r"(ra), "f"(h));
                // remote release-arrive: orders THIS thread's DSMEM store for the peer
                asm volatile(
                    "mbarrier.arrive.release.cluster.shared::cluster.b64 _, [%0];"
                    :: "r"(mbar_peer) : "memory");
            }
        }
        if (s < TT - 1) {
            __syncthreads();    // local h visible to all threads for next own-half dot
        }
    }
#undef DOT_HALF
#undef MBAR_WAIT
}

// ---------------- head: out[b] = y2[b][T-1][:] . lin_w + lin_b ----------------
__global__ void head_kernel(const float* __restrict__ y2, const float* __restrict__ w,
                            const float* __restrict__ bb, float* __restrict__ out) {
    int b   = blockIdx.x;
    int tid = threadIdx.x;  // 128
    const float* row = y2 + ((size_t)b * TT + (TT - 1)) * 256;
    float p = row[tid] * w[tid] + row[tid + 128] * w[tid + 128];
    __shared__ float red[4];
#pragma unroll
    for (int off = 16; off; off >>= 1) p += __shfl_down_sync(0xffffffffu, p, off);
    if ((tid & 31) == 0) red[tid >> 5] = p;
    __syncthreads();
    if (tid == 0) out[b] = red[0] + red[1] + red[2] + red[3] + bb[0];
}

// ---------------- host orchestration (graph-capturable, alloc-free) ----------------
extern "C" void kernel_launch(void* const* d_in, const int* in_sizes, int n_in,
                              void* d_out, int out_size) {
    const int*   X     = (const int*)d_in[0];
    const float* emb   = (const float*)d_in[1];
    const float* hx    = (const float*)d_in[2];
    const float* cx    = (const float*)d_in[3];
    const float* lin_w = (const float*)d_in[4];
    const float* lin_b = (const float*)d_in[5];
    const float* w_ih[3] = {(const float*)d_in[6],  (const float*)d_in[10], (const float*)d_in[14]};
    const float* w_hh[3] = {(const float*)d_in[7],  (const float*)d_in[11], (const float*)d_in[15]};
    const float* b_ih[3] = {(const float*)d_in[8],  (const float*)d_in[12], (const float*)d_in[16]};
    const float* b_hh[3] = {(const float*)d_in[9],  (const float*)d_in[13], (const float*)d_in[17]};

    float *xe, *y0, *y1, *y2, *xgp;
    cudaGetSymbolAddress((void**)&xe,  g_xe);
    cudaGetSymbolAddress((void**)&y0,  g_y0);
    cudaGetSymbolAddress((void**)&y1,  g_y1);
    cudaGetSymbolAddress((void**)&y2,  g_y2);
    cudaGetSymbolAddress((void**)&xgp, g_xg);

    // dynamic smem for the double-buffered GEMM: 2*128*34*8 + 2*32*132*4 bytes
    const int GEMM_SMEM = 2 * 128 * 34 * 8 + 2 * 32 * 132 * 4;   // 103424 B
    cudaFuncSetAttribute(gemm_kernel<EMBD>,
                         cudaFuncAttributeMaxDynamicSharedMemorySize, GEMM_SMEM);
    cudaFuncSetAttribute(gemm_kernel<2 * HH>,
                         cudaFuncAttributeMaxDynamicSharedMemorySize, GEMM_SMEM);

    embed_kernel<<<(BB * TT) / 4, 128>>>(X, emb, xe);
    dummy_kernel<<<1, 32>>>();   // launch-index shim: puts the layer-1 scan at ncu's -s 5

    float*       louts[3] = {y0, y1, y2};
    const float* lins[3]  = {xe, y0, y1};
    for (int l = 0; l < 3; l++) {
        dim3 grid((BB * TT) / 128, 4, 2);   // z = direction
        if (l == 0)
            gemm_kernel<EMBD><<<grid, 256, GEMM_SMEM>>>(lins[l], w_ih[l], b_ih[l], b_hh[l], xgp);
        else
            gemm_kernel<2 * HH><<<grid, 256, GEMM_SMEM>>>(lins[l], w_ih[l], b_ih[l], b_hh[l], xgp);

        cudaLaunchConfig_t cfg = {};
        cfg.gridDim          = dim3(128, 1, 1);
        cfg.blockDim         = dim3(256, 1, 1);
        cfg.dynamicSmemBytes = 0;
        cfg.stream           = 0;
        cudaLaunchAttribute attr[1];
        attr[0].id               = cudaLaunchAttributeClusterDimension;
        attr[0].val.clusterDim.x = 2;
        attr[0].val.clusterDim.y = 1;
        attr[0].val.clusterDim.z = 1;
        cfg.attrs    = attr;
        cfg.numAttrs = 1;
        cudaLaunchKernelEx(&cfg, lstm_scan_kernel, (const float*)xgp, w_hh[l],
                           hx + (size_t)l * 2 * BB * HH, cx + (size_t)l * 2 * BB * HH,
                           louts[l]);
    }

    head_kernel<<<BB, 128>>>(y2, lin_w, lin_b, (float*)d_out);
}

// round 17
// speedup vs baseline: 1.0282x; 1.0282x over previous
#include <cuda_runtime.h>
#include <cstdint>

#define BB   64
#define TT   512
#define HH   128
#define EMBD 128

// ---------------- scratch (device globals: allocation-free) ----------------
__device__ float g_xe[BB * TT * EMBD];          // embed output
__device__ float g_y0[BB * TT * 2 * HH];        // layer0 output
__device__ float g_y1[BB * TT * 2 * HH];        // layer1 output
__device__ float g_y2[BB * TT * 2 * HH];        // layer2 output
__device__ float g_xg[2ull * BB * TT * 4 * HH]; // input-GEMM gates

typedef unsigned long long u64;

__device__ __forceinline__ u64 fma2(u64 a, u64 b, u64 c) {
    u64 d;
    asm("fma.rn.f32x2 %0, %1, %2, %3;" : "=l"(d) : "l"(a), "l"(b), "l"(c));
    return d;
}
__device__ __forceinline__ u64 pack2(float lo, float hi) {
    u64 r;
    asm("mov.b64 %0, {%1, %2};" : "=l"(r) : "f"(lo), "f"(hi));
    return r;
}
__device__ __forceinline__ void unpack2(u64 v, float& lo, float& hi) {
    asm("mov.b64 {%0, %1}, %2;" : "=f"(lo), "=f"(hi) : "l"(v));
}
__device__ __forceinline__ float sigf(float x) {
    return __fdividef(1.f, 1.f + __expf(-x));
}
__device__ __forceinline__ float tanh_f(float x) {
    float cl = fminf(fmaxf(x, -15.f), 15.f);
    float e  = __expf(2.f * cl);
    return __fdividef(e - 1.f, e + 1.f);
}

// ---------------- embedding lookup ----------------
__global__ void embed_kernel(const int* __restrict__ X, const float* __restrict__ emb,
                             float* __restrict__ out) {
    int row  = blockIdx.x * 4 + (threadIdx.x >> 5);
    int lane = threadIdx.x & 31;
    int tok  = X[row];
    float4 v = reinterpret_cast<const float4*>(emb + (size_t)tok * EMBD)[lane];
    reinterpret_cast<float4*>(out + (size_t)row * EMBD)[lane] = v;
}

// dummy launch: shifts ncu's (-s 5 -c 1) capture window onto the layer-1 scan kernel
__global__ void dummy_kernel() {}

// ---------------- input GEMM:  C[m][n] = A[m][:] . W[n][:] + (bih[n]+bhh[n]) ------------
// A: [32768 x K] row-major, W(per dir): [512 x K] row-major, C: [32768 x 512] row-major.
// blockIdx.z = direction. 128x128 tile, 256 threads, 8x8 microtile.
// SINGLE-buffer smem (51.7KB dynamic) + __launch_bounds__(256,2) -> 2 CTAs/SM (occ
// 25%): cross-CTA overlap hides tile-boundary LDG latency (measured occ=12.5% was
// the R3 bottleneck). As2 pre-duplicated (a,a) u64 pairs: one LDS.128 = 2 ready
// f32x2 multiplicands, zero pack MOVs in the hot loop.
template <int K>
__global__ void __launch_bounds__(256, 2) gemm_kernel(
    const float* __restrict__ Amat, const float* __restrict__ Wbase,
    const float* __restrict__ bih_base, const float* __restrict__ bhh_base,
    float* __restrict__ Cbase) {
    extern __shared__ __align__(16) char smem_raw[];
    u64*   As2 = reinterpret_cast<u64*>(smem_raw);                    // [128][34]
    float* Bs  = reinterpret_cast<float*>(smem_raw + 128 * 34 * 8);   // [32][132]

    int z = blockIdx.z;
    const float* Wmat = Wbase + (size_t)z * 512 * K;
    const float* bih  = bih_base + (size_t)z * 512;
    const float* bhh  = bhh_base + (size_t)z * 512;
    float*       Cmat = Cbase + (size_t)z * BB * TT * 512;

    int tid = threadIdx.x;
    int m0  = blockIdx.x * 128;
    int n0  = blockIdx.y * 128;
    int tx  = tid & 15;             // n micro
    int ty  = tid >> 4;             // m micro
    int r8  = tid >> 3;             // 0..31  (load row)
    int c8  = tid & 7;              // 0..7   (load k-float4)

    const float* aptr = Amat + (size_t)(m0 + r8) * K + c8 * 4;
    const float* wptr = Wmat + (size_t)(n0 + r8) * K + c8 * 4;

    float bias[8];
#pragma unroll
    for (int j = 0; j < 4; j++) {
        bias[j]     = bih[n0 + tx * 4 + j]      + bhh[n0 + tx * 4 + j];
        bias[j + 4] = bih[n0 + 64 + tx * 4 + j] + bhh[n0 + 64 + tx * 4 + j];
    }

    u64 acc[8][4];
#pragma unroll
    for (int i = 0; i < 8; i++)
#pragma unroll
        for (int j = 0; j < 4; j++) acc[i][j] = 0ull;

#pragma unroll
    for (int kt = 0; kt < K; kt += 32) {
#pragma unroll
        for (int ii = 0; ii < 4; ii++) {
            float4 va = *reinterpret_cast<const float4*>(aptr + (size_t)ii * 32 * K + kt);
            u64* arow = As2 + ((size_t)(r8 + ii * 32)) * 34 + c8 * 4;
            arow[0] = pack2(va.x, va.x);
            arow[1] = pack2(va.y, va.y);
            arow[2] = pack2(va.z, va.z);
            arow[3] = pack2(va.w, va.w);
            float4 vb = *reinterpret_cast<const float4*>(wptr + (size_t)ii * 32 * K + kt);
            float* bcol = Bs + ((size_t)(c8 * 4)) * 132 + r8 + ii * 32;
            bcol[0 * 132] = vb.x;
            bcol[1 * 132] = vb.y;
            bcol[2 * 132] = vb.z;
            bcol[3 * 132] = vb.w;
        }
        __syncthreads();
#pragma unroll
        for (int kp = 0; kp < 16; kp++) {   // k-pair: kk = 2*kp, 2*kp+1
            const float* brow0 = Bs + ((size_t)(2 * kp)) * 132;
            const float* brow1 = brow0 + 132;
            ulonglong2 b0A = *reinterpret_cast<const ulonglong2*>(brow0 + tx * 4);
            ulonglong2 b0B = *reinterpret_cast<const ulonglong2*>(brow0 + 64 + tx * 4);
            ulonglong2 b1A = *reinterpret_cast<const ulonglong2*>(brow1 + tx * 4);
            ulonglong2 b1B = *reinterpret_cast<const ulonglong2*>(brow1 + 64 + tx * 4);
#pragma unroll
            for (int i = 0; i < 8; i++) {
                ulonglong2 ad = *reinterpret_cast<const ulonglong2*>(
                    As2 + ((size_t)(ty * 8 + i)) * 34 + kp * 2);
                acc[i][0] = fma2(ad.x, b0A.x, acc[i][0]);
                acc[i][1] = fma2(ad.x, b0A.y, acc[i][1]);
                acc[i][2] = fma2(ad.x, b0B.x, acc[i][2]);
                acc[i][3] = fma2(ad.x, b0B.y, acc[i][3]);
                acc[i][0] = fma2(ad.y, b1A.x, acc[i][0]);
                acc[i][1] = fma2(ad.y, b1A.y, acc[i][1]);
                acc[i][2] = fma2(ad.y, b1B.x, acc[i][2]);
                acc[i][3] = fma2(ad.y, b1B.y, acc[i][3]);
            }
        }
        __syncthreads();
    }

#pragma unroll
    for (int i = 0; i < 8; i++) {
        float o[8];
#pragma unroll
        for (int j = 0; j < 4; j++) unpack2(acc[i][j], o[2 * j], o[2 * j + 1]);
#pragma unroll
        for (int j = 0; j < 8; j++) o[j] += bias[j];
        float* base = Cmat + (size_t)(m0 + ty * 8 + i) * 512 + n0;
        *reinterpret_cast<float4*>(base + tx * 4)      = make_float4(o[0], o[1], o[2], o[3]);
        *reinterpret_cast<float4*>(base + 64 + tx * 4) = make_float4(o[4], o[5], o[6], o[7]);
    }
}

// ---------------- recurrent scan: 2-CTA cluster per (dir, batch-pair) ----------------
// Weights REGISTER-RESIDENT (64 u64 k-pairs per thread). SINGLE-ARRIVE mbarrier
// handshake (count=1): after DSMEM h-stores + __syncthreads, tid0 does
// fence.acq_rel.cluster + ONE remote release-arrive (cumulativity over bar.sync
// covers all threads' stores). Replaces 128 serialized same-address remote arrives
// (the R9-measured stall). xg prefetched ONE STEP AHEAD (full-step latency cover).
__global__ void __launch_bounds__(256) lstm_scan_kernel(
    const float* __restrict__ xg,   // [2][B][T][512]
    const float* __restrict__ whh,  // [2][512][128]
    const float* __restrict__ hx,   // [2][B][128]  (this layer)
    const float* __restrict__ cx,   // [2][B][128]
    float* __restrict__ y) {        // [B][T][256]
    __shared__ __align__(16) float hbuf[2][2][128]; // double-buffered h, [buf][b][k]
    __shared__ __align__(8)  float gbuf[256 * 2];   // gate exchange [gl][b]
    __shared__ float cbuf[2 * 64];                  // own-half cell state
    __shared__ __align__(8) u64 mbar;               // peer-arrival barrier (count=1)

    int tid = threadIdx.x;
    uint32_t r;
    asm("mov.u32 %0, %%cluster_ctarank;" : "=r"(r));
    int cid = blockIdx.x >> 1;
    int dir = cid >> 5;
    int b0  = (cid & 31) * 2;

    // ---- load this thread's weight row into registers (64 u64 k-pairs) ----
    int gl  = tid;
    int row = ((gl >> 6) << 7) + (int)r * 64 + (gl & 63);  // gate_q*128 + r*64 + u
    u64 w[64];
    {
        const ulonglong2* wq =
            reinterpret_cast<const ulonglong2*>(whh + ((size_t)dir * 512 + row) * 128);
#pragma unroll
        for (int i = 0; i < 32; i++) {
            ulonglong2 v = wq[i];
            w[2 * i]     = v.x;
            w[2 * i + 1] = v.y;
        }
    }

    uint32_t mbar_local = (uint32_t)__cvta_generic_to_shared(&mbar);
    uint32_t mbar_peer;
    asm("mapa.shared::cluster.u32 %0, %1, %2;"
        : "=r"(mbar_peer) : "r"(mbar_local), "r"(r ^ 1u));

    // ---- init mbarrier (count=1!), h (full, both batches), c (own half) ----
    if (tid == 0) {
        asm volatile("mbarrier.init.shared.b64 [%0], %1;"
                     :: "r"(mbar_local), "r"(1u) : "memory");
    }
    {
        int bb = tid >> 7, k = tid & 127;
        hbuf[0][bb][k] = hx[((size_t)dir * BB + b0 + bb) * HH + k];
        if (tid < 128) {
            int b = tid >> 6, u = tid & 63;
            cbuf[b * 64 + u] = cx[((size_t)dir * BB + b0 + b) * HH + (int)r * 64 + u];
        }
    }
    __syncthreads();
    // one-time full cluster sync: peer's mbarrier.init visible before any remote arrive
    asm volatile("barrier.cluster.arrive.aligned;" ::: "memory");
    asm volatile("barrier.cluster.wait.aligned;"   ::: "memory");

    int eb = tid >> 6;          // epilogue batch (tid<128)
    int eu = tid & 63;          // epilogue unit

    // hoisted xg walking pointer: advances by +512 (fwd) or -512 (bwd) per step
    const float* xp = xg + (((size_t)dir * BB + b0 + eb) * TT + (dir ? TT - 1 : 0)) * 512
                    + (int)r * 64 + eu;
    const intptr_t xstep = dir ? -512 : 512;
    // hoisted y walking pointer (same t ordering)
    float* yp = y + ((size_t)(b0 + eb) * TT + (dir ? TT - 1 : 0)) * 256
              + dir * 128 + (int)r * 64 + eu;
    const intptr_t ystep = dir ? -256 : 256;

    // spin-wait (acquire, cluster scope) on own mbarrier phase parity
#define MBAR_WAIT(par)                                                                \
    do {                                                                              \
        uint32_t _done;                                                               \
        asm volatile(                                                                 \
            "{\n\t.reg .pred p;\n\t"                                                  \
            "mbarrier.try_wait.parity.acquire.cluster.shared::cta.b64 p, [%1], %2;\n\t" \
            "selp.b32 %0, 1, 0, p;\n\t}"                                              \
            : "=r"(_done) : "r"(mbar_local), "r"((uint32_t)(par)) : "memory");        \
        while (!_done) {                                                              \
            asm volatile(                                                             \
                "{\n\t.reg .pred p;\n\t"                                              \
                "mbarrier.try_wait.parity.acquire.cluster.shared::cta.b64 p, [%1], %2, 0x989680;\n\t" \
                "selp.b32 %0, 1, 0, p;\n\t}"                                          \
                : "=r"(_done) : "r"(mbar_local), "r"((uint32_t)(par)) : "memory");    \
        }                                                                             \
    } while (0)

    // DOT over k-pairs [P0, P0+32): 2 LDS.128 + 4 FFMA2 per 2 pairs, w from regs.
#define DOT_HALF(P0)                                                                  \
    do {                                                                              \
        _Pragma("unroll")                                                             \
        for (int j = 0; j < 16; j++) {                                                \
            ulonglong2 hv0 =                                                          \
                *reinterpret_cast<const ulonglong2*>(&hbuf[cur][0][2 * ((P0) + 2 * j)]); \
            ulonglong2 hv1 =                                                          \
                *reinterpret_cast<const ulonglong2*>(&hbuf[cur][1][2 * ((P0) + 2 * j)]); \
            a0a = fma2(w[(P0) + 2 * j],     hv0.x, a0a);                              \
            a0b = fma2(w[(P0) + 2 * j + 1], hv0.y, a0b);                              \
            a1a = fma2(w[(P0) + 2 * j],     hv1.x, a1a);                              \
            a1b = fma2(w[(P0) + 2 * j + 1], hv1.y, a1b);                              \
        }                                                                             \
    } while (0)

    // xg pipeline: preload step-0 values before the loop
    float xv0 = 0.f, xv1 = 0.f, xv2 = 0.f, xv3 = 0.f;
    if (tid < 128) {
        xv0 = xp[0];
        xv1 = xp[128];
        xv2 = xp[256];
        xv3 = xp[384];
        xp += xstep;
    }

    for (int s = 0; s < TT; s++) {
        int cur = s & 1;
        int nxt = cur ^ 1;

        // consume this step's prefetched xg; issue next step's loads (full-step cover)
        float cx0 = xv0, cx1 = xv1, cx2 = xv2, cx3 = xv3;
        if (tid < 128 && s + 1 < TT) {
            xv0 = xp[0];
            xv1 = xp[128];
            xv2 = xp[256];
            xv3 = xp[384];
            xp += xstep;
        }

        u64 a0a = 0ull, a0b = 0ull, a1a = 0ull, a1b = 0ull;
        // own-written k-half first (no cluster dependency), wait hides mid-dot.
        // wait parity: phase s-1 completes via peer's end-of-step-(s-1) arrive
        if (r == 0) {
            DOT_HALF(0);                    // k [0,64) written locally by rank 0
            if (s > 0) MBAR_WAIT(nxt);      // (s-1)&1 == nxt
            DOT_HALF(32);                   // k [64,128) written remotely by rank 1
        } else {
            DOT_HALF(32);
            if (s > 0) MBAR_WAIT(nxt);
            DOT_HALF(0);
        }

        // complete gate values (lo=even-k partial, hi=odd-k partial)
        float e0, o0, e1, o1, e2, o2, e3, o3;
        unpack2(a0a, e0, o0);
        unpack2(a0b, e1, o1);
        unpack2(a1a, e2, o2);
        unpack2(a1b, e3, o3);
        float g0 = (e0 + o0) + (e1 + o1);   // batch 0
        float g1 = (e2 + o2) + (e3 + o3);   // batch 1
        *reinterpret_cast<float2*>(&gbuf[gl * 2]) = make_float2(g0, g1);
        __syncthreads();

        if (tid < 128) {
            int b = eb, u = eu;
            float gi = gbuf[(u)       * 2 + b] + cx0;
            float gf = gbuf[(64 + u)  * 2 + b] + cx1;
            float gg = gbuf[(128 + u) * 2 + b] + cx2;
            float go = gbuf[(192 + u) * 2 + b] + cx3;
            float i_ = sigf(gi), f_ = sigf(gf), o_ = sigf(go), gz = tanh_f(gg);
            float c = f_ * cbuf[b * 64 + u] + i_ * gz;
            cbuf[b * 64 + u] = c;
            float h = o_ * tanh_f(c);

            // layer output
            *yp = h;
            yp += ystep;

            if (s < TT - 1) {
                float* hl = &hbuf[nxt][b][(int)r * 64 + u];
                *hl = h;    // own half, local buffer
                // own half -> peer's buffer (DSMEM)
                uint32_t la = (uint32_t)__cvta_generic_to_shared(hl);
                uint32_t ra;
                asm("mapa.shared::cluster.u32 %0, %1, %2;" : "=r"(ra) : "r"(la), "r"(r ^ 1u));
                asm volatile("st.shared::cluster.f32 [%0], %1;" :: "r"(ra), "f"(h));
            }
        }
        if (s < TT - 1) {
            __syncthreads();    // local h visible; all DSMEM stores issued
            if (tid == 0) {
                // cumulative release: one arrive covers all 128 threads' DSMEM stores
                asm volatile("fence.acq_rel.cluster;" ::: "memory");
                asm volatile(
                    "mbarrier.arrive.release.cluster.shared::cluster.b64 _, [%0];"
                    :: "r"(mbar_peer) : "memory");
            }
        }
    }
#undef DOT_HALF
#undef MBAR_WAIT
}

// ---------------- head: out[b] = y2[b][T-1][:] . lin_w + lin_b ----------------
__global__ void head_kernel(const float* __restrict__ y2, const float* __restrict__ w,
                            const float* __restrict__ bb, float* __restrict__ out) {
    int b   = blockIdx.x;
    int tid = threadIdx.x;  // 128
    const float* row = y2 + ((size_t)b * TT + (TT - 1)) * 256;
    float p = row[tid] * w[tid] + row[tid + 128] * w[tid + 128];
    __shared__ float red[4];
#pragma unroll
    for (int off = 16; off; off >>= 1) p += __shfl_down_sync(0xffffffffu, p, off);
    if ((tid & 31) == 0) red[tid >> 5] = p;
    __syncthreads();
    if (tid == 0) out[b] = red[0] + red[1] + red[2] + red[3] + bb[0];
}

// ---------------- host orchestration (graph-capturable, alloc-free) ----------------
extern "C" void kernel_launch(void* const* d_in, const int* in_sizes, int n_in,
                              void* d_out, int out_size) {
    const int*   X     = (const int*)d_in[0];
    const float* emb   = (const float*)d_in[1];
    const float* hx    = (const float*)d_in[2];
    const float* cx    = (const float*)d_in[3];
    const float* lin_w = (const float*)d_in[4];
    const float* lin_b = (const float*)d_in[5];
    const float* w_ih[3] = {(const float*)d_in[6],  (const float*)d_in[10], (const float*)d_in[14]};
    const float* w_hh[3] = {(const float*)d_in[7],  (const float*)d_in[11], (const float*)d_in[15]};
    const float* b_ih[3] = {(const float*)d_in[8],  (const float*)d_in[12], (const float*)d_in[16]};
    const float* b_hh[3] = {(const float*)d_in[9],  (const float*)d_in[13], (const float*)d_in[17]};

    float *xe, *y0, *y1, *y2, *xgp;
    cudaGetSymbolAddress((void**)&xe,  g_xe);
    cudaGetSymbolAddress((void**)&y0,  g_y0);
    cudaGetSymbolAddress((void**)&y1,  g_y1);
    cudaGetSymbolAddress((void**)&y2,  g_y2);
    cudaGetSymbolAddress((void**)&xgp, g_xg);

    // dynamic smem for the single-buffer GEMM: 128*34*8 + 32*132*4 = 51712 B
    const int GEMM_SMEM = 128 * 34 * 8 + 32 * 132 * 4;
    cudaFuncSetAttribute(gemm_kernel<EMBD>,
                         cudaFuncAttributeMaxDynamicSharedMemorySize, GEMM_SMEM);
    cudaFuncSetAttribute(gemm_kernel<2 * HH>,
                         cudaFuncAttributeMaxDynamicSharedMemorySize, GEMM_SMEM);

    embed_kernel<<<(BB * TT) / 4, 128>>>(X, emb, xe);
    dummy_kernel<<<1, 32>>>();   // launch-index shim: puts the layer-1 scan at ncu's -s 5

    float*       louts[3] = {y0, y1, y2};
    const float* lins[3]  = {xe, y0, y1};
    for (int l = 0; l < 3; l++) {
        dim3 grid((BB * TT) / 128, 4, 2);   // z = direction
        if (l == 0)
            gemm_kernel<EMBD><<<grid, 256, GEMM_SMEM>>>(lins[l], w_ih[l], b_ih[l], b_hh[l], xgp);
        else
            gemm_kernel<2 * HH><<<grid, 256, GEMM_SMEM>>>(lins[l], w_ih[l], b_ih[l], b_hh[l], xgp);

        cudaLaunchConfig_t cfg = {};
        cfg.gridDim          = dim3(128, 1, 1);
        cfg.blockDim         = dim3(256, 1, 1);
        cfg.dynamicSmemBytes = 0;
        cfg.stream           = 0;
        cudaLaunchAttribute attr[1];
        attr[0].id               = cudaLaunchAttributeClusterDimension;
        attr[0].val.clusterDim.x = 2;
        attr[0].val.clusterDim.y = 1;
        attr[0].val.clusterDim.z = 1;
        cfg.attrs    = attr;
        cfg.numAttrs = 1;
        cudaLaunchKernelEx(&cfg, lstm_scan_kernel, (const float*)xgp, w_hh[l],
                           hx + (size_t)l * 2 * BB * HH, cx + (size_t)l * 2 * BB * HH,
                           louts[l]);
    }

    head_kernel<<<BB, 128>>>(y2, lin_w, lin_b, (float*)d_out);
}